// round 5
// baseline (speedup 1.0000x reference)
#include <cuda_runtime.h>

// Scratch (no allocation allowed): per-node gate values, N = 100000 <= 131072.
#define MAX_NODES (1 << 17)
__device__ float g_gate[MAX_NODES];
__device__ int   g_is64;   // 1 if edge_index is int64, 0 if int32

#define PERSISTENT_BLOCKS 1184   // 148 SMs * 8 resident 256-thread CTAs

// ---------------------------------------------------------------------------
// Kernel 1: gate[n] = sigmoid(dot(x[n,:], p) + b). Warp-per-row GEMV with a
// GRID-STRIDE loop over rows (persistent blocks -> no wave transitions).
// p staged in shared. Block 0 also detects index width once (int64 -> all
// high words zero; int32 odd words are random ids, P(all zero) ~ 0).
// ---------------------------------------------------------------------------
__global__ void __launch_bounds__(256) gate_kernel(
        const float* __restrict__ x,
        const float* __restrict__ p,
        const float* __restrict__ bptr,
        int N, int D,
        const int* __restrict__ ei32, int ei_words) {
    __shared__ float p_sh[1024];
    int tid = threadIdx.x;
    for (int i = tid; i < D; i += blockDim.x) p_sh[i] = p[i];

    if (blockIdx.x == 0) {
        __shared__ int nz;
        if (tid == 0) nz = 0;
        __syncthreads();
        int limit = 2048;
        if (limit * 2 > ei_words) limit = ei_words / 2;
        int c = 0;
        for (int i = tid; i < limit; i += blockDim.x)
            if (ei32[2 * i + 1] != 0) c = 1;
        if (c) atomicOr(&nz, 1);
        __syncthreads();
        if (tid == 0) g_is64 = (nz == 0) ? 1 : 0;
    }
    __syncthreads();

    int warp = tid >> 5;
    int lane = tid & 31;
    int rows_per_blk = blockDim.x >> 5;          // 8
    int stride = gridDim.x * rows_per_blk;
    int nvec = D >> 2;
    float bias = bptr[0];

    for (int row = blockIdx.x * rows_per_blk + warp; row < N; row += stride) {
        const float4* xr = reinterpret_cast<const float4*>(x + (long long)row * D);
        float sum = 0.0f;
        for (int i = lane; i < nvec; i += 32) {
            float4 xv = xr[i];
            float4 pv = reinterpret_cast<const float4*>(p_sh)[i];
            sum = fmaf(xv.x, pv.x, sum);
            sum = fmaf(xv.y, pv.y, sum);
            sum = fmaf(xv.z, pv.z, sum);
            sum = fmaf(xv.w, pv.w, sum);
        }
        #pragma unroll
        for (int o = 16; o > 0; o >>= 1)
            sum += __shfl_down_sync(0xffffffffu, sum, o);

        if (lane == 0) {
            float v = sum + bias;
            g_gate[row] = 1.0f / (1.0f + __expf(-v));
        }
    }
}

// ---------------------------------------------------------------------------
// Kernel 2: adj[e] = attr[e] * gate[col[e]]; optional index passthrough as
// float (ids < 2^24, exact). 4 edges per thread-iteration, 16B vector memops,
// plain loads/stores, GRID-STRIDE over 4-edge groups. int64 rows viewed as
// int4 word-pairs -> cheap I2F on low words.
// ---------------------------------------------------------------------------
template <bool FULL>
__global__ void __launch_bounds__(256) edge_kernel(
        const void* __restrict__ eiv,
        const float* __restrict__ attr,
        float* __restrict__ out, int E) {
    const int is64 = g_is64;
    int ngroups = (E + 3) >> 2;
    int stride = gridDim.x * blockDim.x;

    for (int g = blockIdx.x * blockDim.x + threadIdx.x; g < ngroups; g += stride) {
        int e = g << 2;
        if (e + 3 < E) {
            float4 av = reinterpret_cast<const float4*>(attr)[g];
            float4 adj, o0, o1;
            if (is64) {
                // int64 rows viewed as int words: int4 = {lo0, hi0, lo1, hi1}
                const int4* r1p = reinterpret_cast<const int4*>((const long long*)eiv + E);
                int4 b0 = r1p[2 * g];
                int4 b1 = r1p[2 * g + 1];
                adj.x = av.x * g_gate[b0.x];
                adj.y = av.y * g_gate[b0.z];
                adj.z = av.z * g_gate[b1.x];
                adj.w = av.w * g_gate[b1.z];
                if (FULL) {
                    const int4* r0p = reinterpret_cast<const int4*>(eiv);
                    int4 a0 = r0p[2 * g];
                    int4 a1 = r0p[2 * g + 1];
                    o0 = make_float4(__int2float_rn(a0.x), __int2float_rn(a0.z),
                                     __int2float_rn(a1.x), __int2float_rn(a1.z));
                    o1 = make_float4(__int2float_rn(b0.x), __int2float_rn(b0.z),
                                     __int2float_rn(b1.x), __int2float_rn(b1.z));
                }
            } else {
                const int* ei = (const int*)eiv;
                int4 b = reinterpret_cast<const int4*>(ei + E)[g];
                adj.x = av.x * g_gate[b.x];
                adj.y = av.y * g_gate[b.y];
                adj.z = av.z * g_gate[b.z];
                adj.w = av.w * g_gate[b.w];
                if (FULL) {
                    int4 a = reinterpret_cast<const int4*>(ei)[g];
                    o0 = make_float4(__int2float_rn(a.x), __int2float_rn(a.y),
                                     __int2float_rn(a.z), __int2float_rn(a.w));
                    o1 = make_float4(__int2float_rn(b.x), __int2float_rn(b.y),
                                     __int2float_rn(b.z), __int2float_rn(b.w));
                }
            }
            if (FULL) {
                reinterpret_cast<float4*>(out)[g] = o0;
                reinterpret_cast<float4*>(out + E)[g] = o1;
                reinterpret_cast<float4*>(out + 2 * (size_t)E)[g] = adj;
            } else {
                reinterpret_cast<float4*>(out)[g] = adj;
            }
        } else {
            for (int k = e; k < E; k++) {
                int c0, c1;
                if (is64) {
                    const long long* ei = (const long long*)eiv;
                    c0 = (int)ei[k];
                    c1 = (int)ei[E + k];
                } else {
                    const int* ei = (const int*)eiv;
                    c0 = ei[k];
                    c1 = ei[E + k];
                }
                float a = attr[k] * g_gate[c1];
                if (FULL) {
                    out[k]                 = (float)c0;
                    out[(size_t)E + k]     = (float)c1;
                    out[2 * (size_t)E + k] = a;
                } else {
                    out[k] = a;
                }
            }
        }
    }
}

// ---------------------------------------------------------------------------
// Inputs (metadata order): x [N*D] f32, edge_index [2*E] (i32 or i64),
//                          edge_attr [E] f32, p [D] f32, b [1] f32
// ---------------------------------------------------------------------------
extern "C" void kernel_launch(void* const* d_in, const int* in_sizes, int n_in,
                              void* d_out, int out_size) {
    const float* x    = (const float*)d_in[0];
    const void*  ei   = d_in[1];
    const float* attr = (const float*)d_in[2];
    const float* p    = (const float*)d_in[3];
    const float* b    = (const float*)d_in[4];
    float* out = (float*)d_out;

    int ND = in_sizes[0];
    int E  = in_sizes[2];
    int D  = in_sizes[3];
    int N  = ND / D;

    // Kernel 1: per-node gates (+ index-width detection in block 0).
    int rows_per_block = 256 / 32;
    int gwork = (N + rows_per_block - 1) / rows_per_block;
    int gblocks = gwork < PERSISTENT_BLOCKS ? gwork : PERSISTENT_BLOCKS;
    gate_kernel<<<gblocks, 256>>>(x, p, b, N, D, (const int*)ei, in_sizes[1]);

    // Kernel 2: edge scaling (+ optional index passthrough).
    int groups  = (E + 3) / 4;
    int ework   = (groups + 255) / 256;
    int eblocks = ework < PERSISTENT_BLOCKS ? ework : PERSISTENT_BLOCKS;
    if ((long long)out_size >= 3LL * E) {
        edge_kernel<true><<<eblocks, 256>>>(ei, attr, out, E);
    } else {
        edge_kernel<false><<<eblocks, 256>>>(ei, attr, out, E);
    }
}

// round 6
// speedup vs baseline: 1.1745x; 1.1745x over previous
#include <cuda_runtime.h>
#include <cuda_fp16.h>

// Scratch (no allocation allowed): per-node gate values as fp16.
// N = 100000 <= 131072. Max rel rounding err 2^-12 ~ 2.4e-4 << 1e-3 tol.
#define MAX_NODES (1 << 17)
__device__ __align__(16) __half g_gate_h[MAX_NODES];

// ---------------------------------------------------------------------------
// Kernel 1: gate[n] = sigmoid(dot(x[n,:], p) + b). Warp-per-row GEMV,
// p staged in shared, x read coalesced via float4. Pure R2 form (measured
// ~33us / 6.2 TB/s) — no embedded detection, no persistence.
// ---------------------------------------------------------------------------
__global__ void __launch_bounds__(256) gate_kernel(
        const float* __restrict__ x,
        const float* __restrict__ p,
        const float* __restrict__ bptr,
        int N, int D) {
    __shared__ float p_sh[1024];
    int tid = threadIdx.x;
    for (int i = tid; i < D; i += blockDim.x) p_sh[i] = p[i];
    __syncthreads();

    int warp = tid >> 5;
    int lane = tid & 31;
    int row  = blockIdx.x * (blockDim.x >> 5) + warp;
    if (row >= N) return;

    const float4* xr = reinterpret_cast<const float4*>(x + (long long)row * D);
    float sum = 0.0f;
    int nvec = D >> 2;
    for (int i = lane; i < nvec; i += 32) {
        float4 xv = xr[i];
        float4 pv = reinterpret_cast<const float4*>(p_sh)[i];
        sum = fmaf(xv.x, pv.x, sum);
        sum = fmaf(xv.y, pv.y, sum);
        sum = fmaf(xv.z, pv.z, sum);
        sum = fmaf(xv.w, pv.w, sum);
    }
    #pragma unroll
    for (int o = 16; o > 0; o >>= 1)
        sum += __shfl_down_sync(0xffffffffu, sum, o);

    if (lane == 0) {
        float v = sum + bptr[0];
        g_gate_h[row] = __float2half_rn(1.0f / (1.0f + __expf(-v)));
    }
}

// ---------------------------------------------------------------------------
// Kernel 2 (smem variant): persistent CTAs; each CTA stages the full fp16
// gate table into dynamic shared memory, then processes edges with LDS
// gathers (removes ~6.4M L1tex gather wavefronts). Index width (i32 vs i64)
// detected block-locally: int64 ids < 2^31 -> all high words zero; int32 odd
// words are random node ids -> P(all zero) ~ 0.
// ---------------------------------------------------------------------------
template <bool FULL>
__global__ void __launch_bounds__(1024) edge_smem_kernel(
        const void* __restrict__ eiv,
        const float* __restrict__ attr,
        float* __restrict__ out, int E, int N) {
    extern __shared__ __half gate_sh[];
    int tid = threadIdx.x;

    // --- block-local index-width detection ---
    int nz = 0;
    {
        const int* w = (const int*)eiv;
        int lim = E < 2048 ? E : 2048;   // word 2i+1 < 2E always valid
        for (int i = tid; i < lim; i += blockDim.x)
            if (w[2 * i + 1] != 0) nz = 1;
    }
    const int is64 = !__syncthreads_or(nz);

    // --- stage gate table: global fp16 -> smem (16B vector copies) ---
    {
        int nvec = (N * 2 + 15) >> 4;    // uint4 count covering N halfs
        const uint4* src = reinterpret_cast<const uint4*>(g_gate_h);
        uint4* dst = reinterpret_cast<uint4*>(gate_sh);
        for (int i = tid; i < nvec; i += blockDim.x) dst[i] = src[i];
    }
    __syncthreads();

    // --- main loop: 4 edges per thread-iteration, 16B memops ---
    int ngroups = (E + 3) >> 2;
    int stride = gridDim.x * blockDim.x;
    for (int g = blockIdx.x * blockDim.x + tid; g < ngroups; g += stride) {
        int e = g << 2;
        if (e + 3 < E) {
            float4 av = reinterpret_cast<const float4*>(attr)[g];
            float4 adj, o0, o1;
            if (is64) {
                // int64 rows viewed as int words: int4 = {lo0, hi0, lo1, hi1}
                const int4* r1p = reinterpret_cast<const int4*>((const long long*)eiv + E);
                int4 b0 = r1p[2 * g];
                int4 b1 = r1p[2 * g + 1];
                adj.x = av.x * __half2float(gate_sh[b0.x]);
                adj.y = av.y * __half2float(gate_sh[b0.z]);
                adj.z = av.z * __half2float(gate_sh[b1.x]);
                adj.w = av.w * __half2float(gate_sh[b1.z]);
                if (FULL) {
                    const int4* r0p = reinterpret_cast<const int4*>(eiv);
                    int4 a0 = r0p[2 * g];
                    int4 a1 = r0p[2 * g + 1];
                    o0 = make_float4(__int2float_rn(a0.x), __int2float_rn(a0.z),
                                     __int2float_rn(a1.x), __int2float_rn(a1.z));
                    o1 = make_float4(__int2float_rn(b0.x), __int2float_rn(b0.z),
                                     __int2float_rn(b1.x), __int2float_rn(b1.z));
                }
            } else {
                const int* ei = (const int*)eiv;
                int4 b = reinterpret_cast<const int4*>(ei + E)[g];
                adj.x = av.x * __half2float(gate_sh[b.x]);
                adj.y = av.y * __half2float(gate_sh[b.y]);
                adj.z = av.z * __half2float(gate_sh[b.z]);
                adj.w = av.w * __half2float(gate_sh[b.w]);
                if (FULL) {
                    int4 a = reinterpret_cast<const int4*>(ei)[g];
                    o0 = make_float4(__int2float_rn(a.x), __int2float_rn(a.y),
                                     __int2float_rn(a.z), __int2float_rn(a.w));
                    o1 = make_float4(__int2float_rn(b.x), __int2float_rn(b.y),
                                     __int2float_rn(b.z), __int2float_rn(b.w));
                }
            }
            if (FULL) {
                reinterpret_cast<float4*>(out)[g] = o0;
                reinterpret_cast<float4*>(out + E)[g] = o1;
                reinterpret_cast<float4*>(out + 2 * (size_t)E)[g] = adj;
            } else {
                reinterpret_cast<float4*>(out)[g] = adj;
            }
        } else {
            for (int k = e; k < E; k++) {
                int c0, c1;
                if (is64) {
                    const long long* ei = (const long long*)eiv;
                    c0 = (int)ei[k];
                    c1 = (int)ei[E + k];
                } else {
                    const int* ei = (const int*)eiv;
                    c0 = ei[k];
                    c1 = ei[E + k];
                }
                float a = attr[k] * __half2float(gate_sh[c1]);
                if (FULL) {
                    out[k]                 = (float)c0;
                    out[(size_t)E + k]     = (float)c1;
                    out[2 * (size_t)E + k] = a;
                } else {
                    out[k] = a;
                }
            }
        }
    }
}

// ---------------------------------------------------------------------------
// Kernel 2 fallback (L2 gather) for N too large for smem. Same structure,
// gathers from g_gate_h in global.
// ---------------------------------------------------------------------------
template <bool FULL>
__global__ void __launch_bounds__(256) edge_l2_kernel(
        const void* __restrict__ eiv,
        const float* __restrict__ attr,
        float* __restrict__ out, int E) {
    int nz = 0;
    {
        const int* w = (const int*)eiv;
        int lim = E < 2048 ? E : 2048;
        for (int i = threadIdx.x; i < lim; i += blockDim.x)
            if (w[2 * i + 1] != 0) nz = 1;
    }
    const int is64 = !__syncthreads_or(nz);

    int g = blockIdx.x * blockDim.x + threadIdx.x;
    int e = g << 2;
    if (e >= E) return;
    if (e + 3 < E) {
        float4 av = reinterpret_cast<const float4*>(attr)[g];
        float4 adj, o0, o1;
        if (is64) {
            const int4* r1p = reinterpret_cast<const int4*>((const long long*)eiv + E);
            int4 b0 = r1p[2 * g];
            int4 b1 = r1p[2 * g + 1];
            adj.x = av.x * __half2float(g_gate_h[b0.x]);
            adj.y = av.y * __half2float(g_gate_h[b0.z]);
            adj.z = av.z * __half2float(g_gate_h[b1.x]);
            adj.w = av.w * __half2float(g_gate_h[b1.z]);
            if (FULL) {
                const int4* r0p = reinterpret_cast<const int4*>(eiv);
                int4 a0 = r0p[2 * g];
                int4 a1 = r0p[2 * g + 1];
                o0 = make_float4(__int2float_rn(a0.x), __int2float_rn(a0.z),
                                 __int2float_rn(a1.x), __int2float_rn(a1.z));
                o1 = make_float4(__int2float_rn(b0.x), __int2float_rn(b0.z),
                                 __int2float_rn(b1.x), __int2float_rn(b1.z));
            }
        } else {
            const int* ei = (const int*)eiv;
            int4 b = reinterpret_cast<const int4*>(ei + E)[g];
            adj.x = av.x * __half2float(g_gate_h[b.x]);
            adj.y = av.y * __half2float(g_gate_h[b.y]);
            adj.z = av.z * __half2float(g_gate_h[b.z]);
            adj.w = av.w * __half2float(g_gate_h[b.w]);
            if (FULL) {
                int4 a = reinterpret_cast<const int4*>(ei)[g];
                o0 = make_float4(__int2float_rn(a.x), __int2float_rn(a.y),
                                 __int2float_rn(a.z), __int2float_rn(a.w));
                o1 = make_float4(__int2float_rn(b.x), __int2float_rn(b.y),
                                 __int2float_rn(b.z), __int2float_rn(b.w));
            }
        }
        if (FULL) {
            reinterpret_cast<float4*>(out)[g] = o0;
            reinterpret_cast<float4*>(out + E)[g] = o1;
            reinterpret_cast<float4*>(out + 2 * (size_t)E)[g] = adj;
        } else {
            reinterpret_cast<float4*>(out)[g] = adj;
        }
    } else {
        for (int k = e; k < E; k++) {
            int c0, c1;
            if (is64) {
                const long long* ei = (const long long*)eiv;
                c0 = (int)ei[k];
                c1 = (int)ei[E + k];
            } else {
                const int* ei = (const int*)eiv;
                c0 = ei[k];
                c1 = ei[E + k];
            }
            float a = attr[k] * __half2float(g_gate_h[c1]);
            if (FULL) {
                out[k]                 = (float)c0;
                out[(size_t)E + k]     = (float)c1;
                out[2 * (size_t)E + k] = a;
            } else {
                out[k] = a;
            }
        }
    }
}

// ---------------------------------------------------------------------------
// Inputs (metadata order): x [N*D] f32, edge_index [2*E] (i32 or i64),
//                          edge_attr [E] f32, p [D] f32, b [1] f32
// ---------------------------------------------------------------------------
extern "C" void kernel_launch(void* const* d_in, const int* in_sizes, int n_in,
                              void* d_out, int out_size) {
    const float* x    = (const float*)d_in[0];
    const void*  ei   = d_in[1];
    const float* attr = (const float*)d_in[2];
    const float* p    = (const float*)d_in[3];
    const float* b    = (const float*)d_in[4];
    float* out = (float*)d_out;

    int ND = in_sizes[0];
    int E  = in_sizes[2];
    int D  = in_sizes[3];
    int N  = ND / D;

    // Kernel 1: per-node gates (fp16 table).
    int gblocks = (N + 7) / 8;
    gate_kernel<<<gblocks, 256>>>(x, p, b, N, D);

    bool full = ((long long)out_size >= 3LL * E);
    int smem_bytes = ((N * 2 + 15) >> 4) << 4;   // fp16 table, 16B aligned

    if (N <= MAX_NODES && smem_bytes <= 225 * 1024) {
        if (full) {
            cudaFuncSetAttribute(edge_smem_kernel<true>,
                                 cudaFuncAttributeMaxDynamicSharedMemorySize, smem_bytes);
            edge_smem_kernel<true><<<152, 1024, smem_bytes>>>(ei, attr, out, E, N);
        } else {
            cudaFuncSetAttribute(edge_smem_kernel<false>,
                                 cudaFuncAttributeMaxDynamicSharedMemorySize, smem_bytes);
            edge_smem_kernel<false><<<152, 1024, smem_bytes>>>(ei, attr, out, E, N);
        }
    } else {
        int groups  = (E + 3) / 4;
        int eblocks = (groups + 255) / 256;
        if (full) edge_l2_kernel<true><<<eblocks, 256>>>(ei, attr, out, E);
        else      edge_l2_kernel<false><<<eblocks, 256>>>(ei, attr, out, E);
    }
}